// round 1
// baseline (speedup 1.0000x reference)
#include <cuda_runtime.h>

#define N_NODES 100000
#define N_EDGES 3200000
#define N_GRAPHS 64
#define IN_DIM 128
#define HID 64
#define NPART 240
#define SCAN_B 98          // ceil(100000/1024)
#define BN_EPS 1e-5f

// ---------------- device scratch (static, no allocs) ----------------
__device__ int   g_cnt[N_NODES];
__device__ int   g_off[N_NODES + 1];
__device__ int   g_cur[N_NODES];
__device__ int   g_csr[N_EDGES];
__device__ float g_dinv[N_NODES];
__device__ float g_hs[(size_t)N_NODES * HID];   // h * dinv (GEMM output)
__device__ float g_agg[(size_t)N_NODES * HID];  // aggregated (pre-BN)
__device__ float g_part[NPART * 128];           // BN partials
__device__ float g_bn[128];                     // [scale(64), shift(64)]
__device__ float g_emb[N_GRAPHS * HID];
__device__ int   g_bsum[SCAN_B];
__device__ int   g_tmp[N_NODES];

// ---------------- CSR build ----------------
__global__ void k_zero() {
    int i = blockIdx.x * 1024 + threadIdx.x;
    if (i < N_NODES) g_cnt[i] = 0;
}

__global__ void k_count(const int* __restrict__ col) {
    int e = blockIdx.x * blockDim.x + threadIdx.x;
    if (e < N_EDGES) atomicAdd(&g_cnt[col[e]], 1);
}

__global__ void k_scan1() {
    __shared__ int s[1024];
    int i = blockIdx.x * 1024 + threadIdx.x;
    int v = (i < N_NODES) ? g_cnt[i] : 0;
    s[threadIdx.x] = v;
    __syncthreads();
    for (int d = 1; d < 1024; d <<= 1) {
        int t = (threadIdx.x >= d) ? s[threadIdx.x - d] : 0;
        __syncthreads();
        s[threadIdx.x] += t;
        __syncthreads();
    }
    if (i < N_NODES) g_tmp[i] = s[threadIdx.x];
    if (threadIdx.x == 1023) g_bsum[blockIdx.x] = s[1023];
}

__global__ void k_scan2() {
    int run = 0;
    for (int b = 0; b < SCAN_B; b++) { int t = g_bsum[b]; g_bsum[b] = run; run += t; }
}

__global__ void k_scan3() {
    int i = blockIdx.x * 1024 + threadIdx.x;
    if (i < N_NODES) {
        int off = g_tmp[i] + g_bsum[blockIdx.x];
        g_off[i + 1] = off;
        int c = g_cnt[i];
        g_cur[i] = off - c;
        g_dinv[i] = rsqrtf((float)c + 1.0f);
        if (i == 0) g_off[0] = 0;
    }
}

__global__ void k_fill(const int* __restrict__ row, const int* __restrict__ col) {
    int e = blockIdx.x * blockDim.x + threadIdx.x;
    if (e < N_EDGES) {
        int c = col[e];
        int p = atomicAdd(&g_cur[c], 1);
        g_csr[p] = row[e];
    }
}

// ---------------- GEMM: out = (opt BN+ReLU)(in) @ W, epilogue * dinv -> g_hs ----------------
template <int KDIM, bool BNRELU>
__global__ void k_gemm(const float* __restrict__ in, const float* __restrict__ W) {
    __shared__ float xs[64][65];
    __shared__ float ws[64][64];
    int tid = threadIdx.x;
    int nb = blockIdx.x * 64;
    int rm = (tid >> 4) << 2;
    int rn = (tid & 15) << 2;
    float acc[4][4] = {};
    for (int ko = 0; ko < KDIM; ko += 64) {
        #pragma unroll
        for (int t = tid; t < 4096; t += 256) {
            int r = t >> 6, c = t & 63;
            int node = nb + r;
            float v = (node < N_NODES) ? in[(size_t)node * KDIM + ko + c] : 0.0f;
            if (BNRELU) v = fmaxf(v * g_bn[ko + c] + g_bn[64 + ko + c], 0.0f);
            xs[r][c] = v;
        }
        #pragma unroll
        for (int t = tid; t < 4096; t += 256) {
            int r = t >> 6, c = t & 63;
            ws[r][c] = W[(size_t)(ko + r) * HID + c];
        }
        __syncthreads();
        #pragma unroll 16
        for (int kk = 0; kk < 64; kk++) {
            float4 b4 = *(const float4*)&ws[kk][rn];
            #pragma unroll
            for (int i = 0; i < 4; i++) {
                float a = xs[rm + i][kk];
                acc[i][0] += a * b4.x;
                acc[i][1] += a * b4.y;
                acc[i][2] += a * b4.z;
                acc[i][3] += a * b4.w;
            }
        }
        __syncthreads();
    }
    #pragma unroll
    for (int i = 0; i < 4; i++) {
        int node = nb + rm + i;
        if (node < N_NODES) {
            float dv = g_dinv[node];
            float4 o;
            o.x = acc[i][0] * dv; o.y = acc[i][1] * dv;
            o.z = acc[i][2] * dv; o.w = acc[i][3] * dv;
            *(float4*)&g_hs[(size_t)node * HID + rn] = o;
        }
    }
}

// ---------------- aggregation: agg[c] = dinv[c]*(sum_in hs[row] + hs[c]) + bias ----------------
__global__ void k_agg(const float* __restrict__ bias) {
    int w = (blockIdx.x * blockDim.x + threadIdx.x) >> 5;
    int lane = threadIdx.x & 31;
    if (w >= N_NODES) return;
    int s = g_off[w], e = g_off[w + 1];
    float a0 = g_hs[(size_t)w * HID + lane];        // self-loop term
    float a1 = g_hs[(size_t)w * HID + 32 + lane];
    int eb = s;
    for (; eb + 32 <= e; eb += 32) {
        int r = g_csr[eb + lane];
        #pragma unroll
        for (int j = 0; j < 32; j++) {
            int rr = __shfl_sync(0xffffffffu, r, j);
            a0 += g_hs[(size_t)rr * HID + lane];
            a1 += g_hs[(size_t)rr * HID + 32 + lane];
        }
    }
    if (eb < e) {
        int n = e - eb;
        int r = (eb + lane < e) ? g_csr[eb + lane] : 0;
        for (int j = 0; j < n; j++) {
            int rr = __shfl_sync(0xffffffffu, r, j);
            a0 += g_hs[(size_t)rr * HID + lane];
            a1 += g_hs[(size_t)rr * HID + 32 + lane];
        }
    }
    float dv = g_dinv[w];
    g_agg[(size_t)w * HID + lane]      = a0 * dv + bias[lane];
    g_agg[(size_t)w * HID + 32 + lane] = a1 * dv + bias[32 + lane];
}

// ---------------- BN statistics (deterministic 2-stage) ----------------
__global__ void k_bnstat() {
    float s = 0.0f, q = 0.0f;
    const size_t total = (size_t)N_NODES * HID;
    for (size_t i = (size_t)blockIdx.x * 256 + threadIdx.x; i < total; i += (size_t)NPART * 256) {
        float v = g_agg[i];
        s += v;
        q += v * v;
    }
    __shared__ float sh[256], shq[256];
    sh[threadIdx.x] = s; shq[threadIdx.x] = q;
    __syncthreads();
    if (threadIdx.x < 64) {
        float ts = 0.0f, tq = 0.0f;
        for (int j = threadIdx.x; j < 256; j += 64) { ts += sh[j]; tq += shq[j]; }
        g_part[blockIdx.x * 128 + threadIdx.x] = ts;
        g_part[blockIdx.x * 128 + 64 + threadIdx.x] = tq;
    }
}

__global__ void k_bnfinal(const float* __restrict__ gamma, const float* __restrict__ beta) {
    int f = threadIdx.x;
    float s = 0.0f, q = 0.0f;
    for (int b = 0; b < NPART; b++) {
        s += g_part[b * 128 + f];
        q += g_part[b * 128 + 64 + f];
    }
    const float invN = 1.0f / (float)N_NODES;
    float mean = s * invN;
    float var = q * invN - mean * mean;
    float rstd = rsqrtf(var + BN_EPS);
    float scale = rstd * gamma[f];
    g_bn[f] = scale;
    g_bn[64 + f] = beta[f] - mean * scale;
}

// ---------------- graph mean pool with fused BN3 ----------------
__device__ __forceinline__ int lower_bound_i(const int* a, int n, int v) {
    int lo = 0, hi = n;
    while (lo < hi) { int m = (lo + hi) >> 1; if (a[m] < v) lo = m + 1; else hi = m; }
    return lo;
}

__global__ void k_pool(const int* __restrict__ batch) {
    int g = blockIdx.x;
    __shared__ int ss, se;
    if (threadIdx.x == 0) {
        ss = lower_bound_i(batch, N_NODES, g);
        se = lower_bound_i(batch, N_NODES, g + 1);
    }
    __syncthreads();
    int f = threadIdx.x & 63, sub = threadIdx.x >> 6;
    float s = 0.0f;
    for (int n = ss + sub; n < se; n += 4) s += g_agg[(size_t)n * HID + f];
    __shared__ float sh[256];
    sh[threadIdx.x] = s;
    __syncthreads();
    if (threadIdx.x < 64) {
        float tot = sh[threadIdx.x] + sh[threadIdx.x + 64] + sh[threadIdx.x + 128] + sh[threadIdx.x + 192];
        int cnt = se - ss;
        float scale = g_bn[threadIdx.x], shift = g_bn[64 + threadIdx.x];
        float emb = (scale * tot + shift * (float)cnt) / fmaxf((float)cnt, 1.0f);
        g_emb[g * HID + threadIdx.x] = emb;
    }
}

// ---------------- centroid classifier ----------------
__global__ void k_cls(const float* __restrict__ cg, const float* __restrict__ cm,
                      const float* __restrict__ temp, float* __restrict__ out) {
    int g = blockIdx.x;
    __shared__ float e[64];
    __shared__ float dist[197];
    if (threadIdx.x < 64) e[threadIdx.x] = g_emb[g * HID + threadIdx.x];
    __syncthreads();
    for (int c = threadIdx.x; c < 197; c += 256) {
        const float* cp = (c < 5) ? (cg + (size_t)c * HID) : (cm + (size_t)(c - 5) * HID);
        float s = 0.0f;
        #pragma unroll
        for (int k = 0; k < 64; k++) { float d = e[k] - cp[k]; s += d * d; }
        dist[c] = s;
    }
    __syncthreads();
    float t = temp[0];
    if (threadIdx.x == 0) {
        float mg = dist[0];
        for (int c = 1; c < 5; c++) mg = fminf(mg, dist[c]);
        out[g * 65] = -mg / t;
    }
    if (threadIdx.x < 64) {
        int b = 5 + threadIdx.x * 3;
        float m = fminf(fminf(dist[b], dist[b + 1]), dist[b + 2]);
        out[g * 65 + 1 + threadIdx.x] = -m / t;
    }
}

// ---------------- host launcher ----------------
extern "C" void kernel_launch(void* const* d_in, const int* in_sizes, int n_in,
                              void* d_out, int out_size) {
    const float* x    = (const float*)d_in[0];
    const int*   ei   = (const int*)d_in[1];
    const int*   batch= (const int*)d_in[2];
    const float* W1 = (const float*)d_in[3];  const float* b1  = (const float*)d_in[4];
    const float* g1 = (const float*)d_in[5];  const float* be1 = (const float*)d_in[6];
    const float* W2 = (const float*)d_in[7];  const float* b2  = (const float*)d_in[8];
    const float* g2 = (const float*)d_in[9];  const float* be2 = (const float*)d_in[10];
    const float* W3 = (const float*)d_in[11]; const float* b3  = (const float*)d_in[12];
    const float* g3 = (const float*)d_in[13]; const float* be3 = (const float*)d_in[14];
    const float* cg = (const float*)d_in[15]; const float* cm  = (const float*)d_in[16];
    const float* temp = (const float*)d_in[17];
    float* out = (float*)d_out;

    const int* row = ei;
    const int* col = ei + N_EDGES;

    float* aggp = nullptr;
    cudaGetSymbolAddress((void**)&aggp, g_agg);

    const int GEMM_BLOCKS = (N_NODES + 63) / 64;   // 1563
    const int EDGE_BLOCKS = (N_EDGES + 255) / 256; // 12500
    const int WARP_BLOCKS = (N_NODES + 7) / 8;     // 12500 (8 warps/block)

    // CSR build (by destination col)
    k_zero<<<SCAN_B, 1024>>>();
    k_count<<<EDGE_BLOCKS, 256>>>(col);
    k_scan1<<<SCAN_B, 1024>>>();
    k_scan2<<<1, 1>>>();
    k_scan3<<<SCAN_B, 1024>>>();
    k_fill<<<EDGE_BLOCKS, 256>>>(row, col);

    // Layer 1
    k_gemm<IN_DIM, false><<<GEMM_BLOCKS, 256>>>(x, W1);
    k_agg<<<WARP_BLOCKS, 256>>>(b1);
    k_bnstat<<<NPART, 256>>>();
    k_bnfinal<<<1, 64>>>(g1, be1);

    // Layer 2 (BN1+ReLU fused into GEMM load)
    k_gemm<HID, true><<<GEMM_BLOCKS, 256>>>(aggp, W2);
    k_agg<<<WARP_BLOCKS, 256>>>(b2);
    k_bnstat<<<NPART, 256>>>();
    k_bnfinal<<<1, 64>>>(g2, be2);

    // Layer 3
    k_gemm<HID, true><<<GEMM_BLOCKS, 256>>>(aggp, W3);
    k_agg<<<WARP_BLOCKS, 256>>>(b3);
    k_bnstat<<<NPART, 256>>>();
    k_bnfinal<<<1, 64>>>(g3, be3);

    // Pool (BN3 fused) + classifier
    k_pool<<<N_GRAPHS, 256>>>(batch);
    k_cls<<<N_GRAPHS, 256>>>(cg, cm, temp, out);
}

// round 2
// speedup vs baseline: 1.0326x; 1.0326x over previous
#include <cuda_runtime.h>

#define N_NODES 100000
#define N_EDGES 3200000
#define N_GRAPHS 64
#define IN_DIM 128
#define HID 64
#define NPART 240
#define SCAN_B 98          // ceil(100000/1024)
#define BN_EPS 1e-5f

// ---------------- device scratch (static, no allocs) ----------------
__device__ int   g_cnt[N_NODES];
__device__ int   g_off[N_NODES + 1];
__device__ int   g_cur[N_NODES];
__device__ int   g_csr[N_EDGES];
__device__ float g_dinv[N_NODES];
__device__ float g_hs[(size_t)N_NODES * HID];   // h * dinv (GEMM output)
__device__ float g_agg[(size_t)N_NODES * HID];  // aggregated (pre-BN)
__device__ float g_part[NPART * 128];           // BN partials
__device__ float g_bn[128];                     // [scale(64), shift(64)]
__device__ float g_emb[N_GRAPHS * HID];
__device__ int   g_bsum[SCAN_B];
__device__ int   g_tmp[N_NODES];

// ---------------- CSR build ----------------
__global__ void k_zero() {
    int i = blockIdx.x * 1024 + threadIdx.x;
    if (i < N_NODES) g_cnt[i] = 0;
}

__global__ void k_count(const int* __restrict__ col) {
    int e = blockIdx.x * blockDim.x + threadIdx.x;
    if (e < N_EDGES) atomicAdd(&g_cnt[col[e]], 1);
}

__global__ void k_dinv() {
    int i = blockIdx.x * 1024 + threadIdx.x;
    if (i < N_NODES) g_dinv[i] = rsqrtf((float)g_cnt[i] + 1.0f);
}

__global__ void k_scan1() {
    __shared__ int s[1024];
    int i = blockIdx.x * 1024 + threadIdx.x;
    int v = (i < N_NODES) ? g_cnt[i] : 0;
    s[threadIdx.x] = v;
    __syncthreads();
    for (int d = 1; d < 1024; d <<= 1) {
        int t = (threadIdx.x >= d) ? s[threadIdx.x - d] : 0;
        __syncthreads();
        s[threadIdx.x] += t;
        __syncthreads();
    }
    if (i < N_NODES) g_tmp[i] = s[threadIdx.x];
    if (threadIdx.x == 1023) g_bsum[blockIdx.x] = s[1023];
}

// parallel exclusive scan over the 98 block sums (1 block, 128 threads)
__global__ void k_scan2() {
    __shared__ int s[128];
    int v = (threadIdx.x < SCAN_B) ? g_bsum[threadIdx.x] : 0;
    s[threadIdx.x] = v;
    __syncthreads();
    for (int d = 1; d < 128; d <<= 1) {
        int t = (threadIdx.x >= d) ? s[threadIdx.x - d] : 0;
        __syncthreads();
        s[threadIdx.x] += t;
        __syncthreads();
    }
    if (threadIdx.x < SCAN_B) g_bsum[threadIdx.x] = s[threadIdx.x] - v;  // exclusive
}

__global__ void k_scan3() {
    int i = blockIdx.x * 1024 + threadIdx.x;
    if (i < N_NODES) {
        int off = g_tmp[i] + g_bsum[blockIdx.x];
        g_off[i + 1] = off;
        g_cur[i] = off - g_cnt[i];
        if (i == 0) g_off[0] = 0;
    }
}

__global__ void k_fill(const int* __restrict__ row, const int* __restrict__ col) {
    int e = blockIdx.x * blockDim.x + threadIdx.x;
    if (e < N_EDGES) {
        int c = col[e];
        int p = atomicAdd(&g_cur[c], 1);
        g_csr[p] = row[e];
    }
}

// ---------------- GEMM: g_hs = dinv * (opt BN+ReLU)(in) @ W  ----------------
// M-tile 128, N=64 full. 256 threads, each computes 8m x 4n via packed f32x2 FMA.
__device__ __forceinline__ unsigned long long ffma2(unsigned long long a,
                                                    unsigned long long b,
                                                    unsigned long long c) {
    unsigned long long d;
    asm("fma.rn.f32x2 %0, %1, %2, %3;" : "=l"(d) : "l"(a), "l"(b), "l"(c));
    return d;
}

template <int KDIM, bool BNRELU>
__global__ void __launch_bounds__(256, 3) k_gemm(const float* __restrict__ in,
                                                 const float* __restrict__ W) {
    __shared__ float xs[64][130];   // [k][m] transposed, even pad (8B-aligned u64 rows)
    __shared__ float ws[64][65];    // [k][n]
    int tid = threadIdx.x;
    int nb = blockIdx.x * 128;
    int mg = tid >> 4;   // 0..15 -> m base = mg*8
    int ng = tid & 15;   // 0..15 -> n base = ng*4

    unsigned long long acc[4][4];   // [m-pair][n], each holds (m_even, m_odd)
    #pragma unroll
    for (int p = 0; p < 4; p++)
        #pragma unroll
        for (int j = 0; j < 4; j++) acc[p][j] = 0ull;

    for (int ko = 0; ko < KDIM; ko += 64) {
        // load X tile transposed: xs[k][m]
        #pragma unroll
        for (int t = tid; t < 128 * 64; t += 256) {
            int r = t >> 6, c = t & 63;          // r = m row, c = k
            int node = nb + r;
            float v = (node < N_NODES) ? in[(size_t)node * KDIM + ko + c] : 0.0f;
            if (BNRELU) v = fmaxf(v * g_bn[ko + c] + g_bn[64 + ko + c], 0.0f);
            xs[c][r] = v;
        }
        // load W tile: ws[k][n]
        #pragma unroll
        for (int t = tid; t < 4096; t += 256) {
            int r = t >> 6, c = t & 63;
            ws[r][c] = W[(size_t)(ko + r) * HID + c];
        }
        __syncthreads();

        #pragma unroll 8
        for (int kk = 0; kk < 64; kk++) {
            unsigned long long a[4];
            #pragma unroll
            for (int p = 0; p < 4; p++)
                a[p] = *(const unsigned long long*)&xs[kk][mg * 8 + 2 * p];
            #pragma unroll
            for (int j = 0; j < 4; j++) {
                float bv = ws[kk][ng * 4 + j];
                unsigned long long bb;
                asm("mov.b64 %0, {%1, %1};" : "=l"(bb) : "f"(bv));
                #pragma unroll
                for (int p = 0; p < 4; p++)
                    acc[p][j] = ffma2(a[p], bb, acc[p][j]);
            }
        }
        __syncthreads();
    }

    // epilogue: scale by dinv, store float4 per row
    #pragma unroll
    for (int p = 0; p < 4; p++) {
        uint2 u0 = *(uint2*)&acc[p][0];
        uint2 u1 = *(uint2*)&acc[p][1];
        uint2 u2 = *(uint2*)&acc[p][2];
        uint2 u3 = *(uint2*)&acc[p][3];
        int m0 = nb + mg * 8 + 2 * p;
        if (m0 < N_NODES) {
            float dv = g_dinv[m0];
            float4 o;
            o.x = __uint_as_float(u0.x) * dv;
            o.y = __uint_as_float(u1.x) * dv;
            o.z = __uint_as_float(u2.x) * dv;
            o.w = __uint_as_float(u3.x) * dv;
            *(float4*)&g_hs[(size_t)m0 * HID + ng * 4] = o;
        }
        int m1 = m0 + 1;
        if (m1 < N_NODES) {
            float dv = g_dinv[m1];
            float4 o;
            o.x = __uint_as_float(u0.y) * dv;
            o.y = __uint_as_float(u1.y) * dv;
            o.z = __uint_as_float(u2.y) * dv;
            o.w = __uint_as_float(u3.y) * dv;
            *(float4*)&g_hs[(size_t)m1 * HID + ng * 4] = o;
        }
    }
}

// ---------------- aggregation: agg[c] = dinv[c]*(sum_in hs[row] + hs[c]) + bias ----------------
__global__ void k_agg(const float* __restrict__ bias) {
    int w = (blockIdx.x * blockDim.x + threadIdx.x) >> 5;
    int lane = threadIdx.x & 31;
    if (w >= N_NODES) return;
    int s = g_off[w], e = g_off[w + 1];
    float a0 = g_hs[(size_t)w * HID + lane];        // self-loop term
    float a1 = g_hs[(size_t)w * HID + 32 + lane];
    int eb = s;
    for (; eb + 32 <= e; eb += 32) {
        int r = g_csr[eb + lane];
        #pragma unroll
        for (int j = 0; j < 32; j++) {
            int rr = __shfl_sync(0xffffffffu, r, j);
            a0 += __ldg(&g_hs[(size_t)rr * HID + lane]);
            a1 += __ldg(&g_hs[(size_t)rr * HID + 32 + lane]);
        }
    }
    if (eb < e) {
        int n = e - eb;
        int r = (eb + lane < e) ? g_csr[eb + lane] : 0;
        for (int j = 0; j < n; j++) {
            int rr = __shfl_sync(0xffffffffu, r, j);
            a0 += __ldg(&g_hs[(size_t)rr * HID + lane]);
            a1 += __ldg(&g_hs[(size_t)rr * HID + 32 + lane]);
        }
    }
    float dv = g_dinv[w];
    g_agg[(size_t)w * HID + lane]      = a0 * dv + bias[lane];
    g_agg[(size_t)w * HID + 32 + lane] = a1 * dv + bias[32 + lane];
}

// ---------------- BN statistics (deterministic 2-stage) ----------------
__global__ void k_bnstat() {
    float s = 0.0f, q = 0.0f;
    const size_t total = (size_t)N_NODES * HID;
    for (size_t i = (size_t)blockIdx.x * 256 + threadIdx.x; i < total; i += (size_t)NPART * 256) {
        float v = g_agg[i];
        s += v;
        q += v * v;
    }
    __shared__ float sh[256], shq[256];
    sh[threadIdx.x] = s; shq[threadIdx.x] = q;
    __syncthreads();
    if (threadIdx.x < 64) {
        float ts = 0.0f, tq = 0.0f;
        for (int j = threadIdx.x; j < 256; j += 64) { ts += sh[j]; tq += shq[j]; }
        g_part[blockIdx.x * 128 + threadIdx.x] = ts;
        g_part[blockIdx.x * 128 + 64 + threadIdx.x] = tq;
    }
}

__global__ void k_bnfinal(const float* __restrict__ gamma, const float* __restrict__ beta) {
    int f = threadIdx.x;
    float s = 0.0f, q = 0.0f;
    for (int b = 0; b < NPART; b++) {
        s += g_part[b * 128 + f];
        q += g_part[b * 128 + 64 + f];
    }
    const float invN = 1.0f / (float)N_NODES;
    float mean = s * invN;
    float var = q * invN - mean * mean;
    float rstd = rsqrtf(var + BN_EPS);
    float scale = rstd * gamma[f];
    g_bn[f] = scale;
    g_bn[64 + f] = beta[f] - mean * scale;
}

// ---------------- graph mean pool with fused BN3 ----------------
__device__ __forceinline__ int lower_bound_i(const int* a, int n, int v) {
    int lo = 0, hi = n;
    while (lo < hi) { int m = (lo + hi) >> 1; if (a[m] < v) lo = m + 1; else hi = m; }
    return lo;
}

__global__ void k_pool(const int* __restrict__ batch) {
    int g = blockIdx.x;
    __shared__ int ss, se;
    if (threadIdx.x == 0) {
        ss = lower_bound_i(batch, N_NODES, g);
        se = lower_bound_i(batch, N_NODES, g + 1);
    }
    __syncthreads();
    int f = threadIdx.x & 63, sub = threadIdx.x >> 6;
    float s = 0.0f;
    for (int n = ss + sub; n < se; n += 4) s += g_agg[(size_t)n * HID + f];
    __shared__ float sh[256];
    sh[threadIdx.x] = s;
    __syncthreads();
    if (threadIdx.x < 64) {
        float tot = sh[threadIdx.x] + sh[threadIdx.x + 64] + sh[threadIdx.x + 128] + sh[threadIdx.x + 192];
        int cnt = se - ss;
        float scale = g_bn[threadIdx.x], shift = g_bn[64 + threadIdx.x];
        float emb = (scale * tot + shift * (float)cnt) / fmaxf((float)cnt, 1.0f);
        g_emb[g * HID + threadIdx.x] = emb;
    }
}

// ---------------- centroid classifier ----------------
__global__ void k_cls(const float* __restrict__ cg, const float* __restrict__ cm,
                      const float* __restrict__ temp, float* __restrict__ out) {
    int g = blockIdx.x;
    __shared__ float e[64];
    __shared__ float dist[197];
    if (threadIdx.x < 64) e[threadIdx.x] = g_emb[g * HID + threadIdx.x];
    __syncthreads();
    for (int c = threadIdx.x; c < 197; c += 256) {
        const float* cp = (c < 5) ? (cg + (size_t)c * HID) : (cm + (size_t)(c - 5) * HID);
        float s = 0.0f;
        #pragma unroll
        for (int k = 0; k < 64; k++) { float d = e[k] - cp[k]; s += d * d; }
        dist[c] = s;
    }
    __syncthreads();
    float t = temp[0];
    if (threadIdx.x == 0) {
        float mg = dist[0];
        for (int c = 1; c < 5; c++) mg = fminf(mg, dist[c]);
        out[g * 65] = -mg / t;
    }
    if (threadIdx.x < 64) {
        int b = 5 + threadIdx.x * 3;
        float m = fminf(fminf(dist[b], dist[b + 1]), dist[b + 2]);
        out[g * 65 + 1 + threadIdx.x] = -m / t;
    }
}

// ---------------- host launcher ----------------
extern "C" void kernel_launch(void* const* d_in, const int* in_sizes, int n_in,
                              void* d_out, int out_size) {
    const float* x    = (const float*)d_in[0];
    const int*   ei   = (const int*)d_in[1];
    const int*   batch= (const int*)d_in[2];
    const float* W1 = (const float*)d_in[3];  const float* b1  = (const float*)d_in[4];
    const float* g1 = (const float*)d_in[5];  const float* be1 = (const float*)d_in[6];
    const float* W2 = (const float*)d_in[7];  const float* b2  = (const float*)d_in[8];
    const float* g2 = (const float*)d_in[9];  const float* be2 = (const float*)d_in[10];
    const float* W3 = (const float*)d_in[11]; const float* b3  = (const float*)d_in[12];
    const float* g3 = (const float*)d_in[13]; const float* be3 = (const float*)d_in[14];
    const float* cg = (const float*)d_in[15]; const float* cm  = (const float*)d_in[16];
    const float* temp = (const float*)d_in[17];
    float* out = (float*)d_out;

    const int* row = ei;
    const int* col = ei + N_EDGES;

    float* aggp = nullptr;
    cudaGetSymbolAddress((void**)&aggp, g_agg);

    const int GEMM_BLOCKS = (N_NODES + 127) / 128; // 782
    const int EDGE_BLOCKS = (N_EDGES + 255) / 256; // 12500
    const int WARP_BLOCKS = (N_NODES + 7) / 8;     // 12500 (8 warps/block)

    // CSR build front half; dinv early so GEMM1 is the 4th launch (ncu -s5 target)
    k_zero<<<SCAN_B, 1024>>>();
    k_count<<<EDGE_BLOCKS, 256>>>(col);
    k_dinv<<<SCAN_B, 1024>>>();

    // Layer 1 GEMM (only needs x, W1, dinv)
    k_gemm<IN_DIM, false><<<GEMM_BLOCKS, 256>>>(x, W1);

    // finish CSR build
    k_scan1<<<SCAN_B, 1024>>>();
    k_scan2<<<1, 128>>>();
    k_scan3<<<SCAN_B, 1024>>>();
    k_fill<<<EDGE_BLOCKS, 256>>>(row, col);

    // Layer 1 aggregate + BN
    k_agg<<<WARP_BLOCKS, 256>>>(b1);
    k_bnstat<<<NPART, 256>>>();
    k_bnfinal<<<1, 64>>>(g1, be1);

    // Layer 2 (BN1+ReLU fused into GEMM load)
    k_gemm<HID, true><<<GEMM_BLOCKS, 256>>>(aggp, W2);
    k_agg<<<WARP_BLOCKS, 256>>>(b2);
    k_bnstat<<<NPART, 256>>>();
    k_bnfinal<<<1, 64>>>(g2, be2);

    // Layer 3
    k_gemm<HID, true><<<GEMM_BLOCKS, 256>>>(aggp, W3);
    k_agg<<<WARP_BLOCKS, 256>>>(b3);
    k_bnstat<<<NPART, 256>>>();
    k_bnfinal<<<1, 64>>>(g3, be3);

    // Pool (BN3 fused) + classifier
    k_pool<<<N_GRAPHS, 256>>>(batch);
    k_cls<<<N_GRAPHS, 256>>>(cg, cm, temp, out);
}